// round 16
// baseline (speedup 1.0000x reference)
#include <cuda_runtime.h>
#include <cuda_fp16.h>
#include <cstdint>

#define ZS   512
#define HHN  511
#define NB   65536

// ------------------------- device scratch (no allocs) -----------------------
__device__ float g_V [HHN * ZS];
__device__ float g_RB[ZS * 1024];
__device__ float g_S [HHN * HHN];
__device__ float g_W [HHN * 1024];
__device__ float g_rrii[ZS];
__device__ float g_ldjp[4 * NB];
__device__ __align__(16) __half g_B1h[ZS * ZS], g_B1l[ZS * ZS]; // [n][k]
__device__ __align__(16) __half g_B2h[ZS * ZS];                 // [zi][n]
__device__ __align__(16) __half g_zh[(size_t)NB * ZS];          // z hi
__device__ __align__(16) __half g_zl[(size_t)NB * ZS];          // z lo
__device__ __align__(16) __half g_hh[(size_t)NB * ZS];          // hB (fp16)

// ------------------------- helpers ------------------------------------------
__device__ __forceinline__ float ftanh(float x) {
    float ax = fabsf(x);
    float e  = __expf(-2.0f * ax);
    float t  = __fdividef(1.0f - e, 1.0f + e);
    return copysignf(t, x);
}
__device__ __forceinline__ uint32_t s2u(const void* p) {
    uint32_t a;
    asm("{ .reg .u64 t; cvta.to.shared.u64 t, %1; cvt.u32.u64 %0, t; }" : "=r"(a) : "l"(p));
    return a;
}
__device__ __forceinline__ void cp16(uint32_t d, const void* s) {
    asm volatile("cp.async.cg.shared.global [%0], [%1], 16;\n" :: "r"(d), "l"(s));
}
#define LDSM4(r0, r1, r2, r3, a) \
    asm volatile("ldmatrix.sync.aligned.m8n8.x4.shared.b16 {%0,%1,%2,%3}, [%4];" \
                 : "=r"(r0), "=r"(r1), "=r"(r2), "=r"(r3) : "r"(a))
#define MMA(c, a, b0, b1) \
    asm volatile("mma.sync.aligned.m16n8k16.row.col.f32.f16.f16.f32 " \
                 "{%0,%1,%2,%3},{%4,%5,%6,%7},{%8,%9},{%0,%1,%2,%3};" \
                 : "+f"((c)[0]), "+f"((c)[1]), "+f"((c)[2]), "+f"((c)[3]) \
                 : "r"((a)[0]), "r"((a)[1]), "r"((a)[2]), "r"((a)[3]), "r"(b0), "r"(b1))
#define MMAH(e, a, b0, b1) \
    asm volatile("mma.sync.aligned.m16n8k16.row.col.f16.f16.f16.f16 " \
                 "{%0,%1},{%2,%3,%4,%5},{%6,%7},{%0,%1};" \
                 : "+r"((e)[0]), "+r"((e)[1]) \
                 : "r"((a)[0]), "r"((a)[1]), "r"((a)[2]), "r"((a)[3]), "r"(b0), "r"(b1))

__device__ __forceinline__ void split_h(float x, __half& h, __half& l) {
    h = __float2half_rn(x);
    l = __float2half_rn(x - __half2float(h));
}

// one z-split block: 2048 floats -> fp16 hi/lo
__device__ __forceinline__ void zsplit_block(const float* __restrict__ z, int zb) {
    size_t base = ((size_t)zb * 256 + threadIdx.x) * 8;
    float4 a = *(const float4*)(z + base);
    float4 b = *(const float4*)(z + base + 4);
    float x[8] = {a.x, a.y, a.z, a.w, b.x, b.y, b.z, b.w};
    __half2 hh[4], ll[4];
#pragma unroll
    for (int i = 0; i < 4; i++) {
        __half h0, l0, h1, l1;
        split_h(x[2 * i], h0, l0);
        split_h(x[2 * i + 1], h1, l1);
        hh[i] = __halves2half2(h0, h1);
        ll[i] = __halves2half2(l0, l1);
    }
    *(uint4*)(g_zh + base) = *(uint4*)hh;
    *(uint4*)(g_zl + base) = *(uint4*)ll;
}

// ------------------------- init: normalize v | build RB ----------------------
__global__ void __launch_bounds__(256) k_init(const float* __restrict__ v,
                                              const float* __restrict__ Rs,
                                              const float* __restrict__ r2d) {
    int tid = threadIdx.x;
    if (blockIdx.x < HHN) {
        int row = blockIdx.x;
        float x0 = v[row * ZS + tid];
        float x1 = v[row * ZS + tid + 256];
        float s = x0 * x0 + x1 * x1;
#pragma unroll
        for (int o = 16; o > 0; o >>= 1) s += __shfl_xor_sync(0xffffffffu, s, o);
        __shared__ float red[8];
        __shared__ float sinv;
        if ((tid & 31) == 0) red[tid >> 5] = s;
        __syncthreads();
        if (tid == 0) {
            float t = 0.f;
#pragma unroll
            for (int i = 0; i < 8; i++) t += red[i];
            sinv = rsqrtf(t);
        }
        __syncthreads();
        float inv = sinv;
        g_V[row * ZS + tid]       = x0 * inv;
        g_V[row * ZS + tid + 256] = x1 * inv;
    } else {
        int idx = (blockIdx.x - HHN) * 256 + tid;
        int i = idx >> 9, j = idx & 511;
        float rs = Rs[i * ZS + j];
        g_RB[i * 1024 + j] = (j >= i) ? rs : 0.f;
        float rst = Rs[j * ZS + i];
        g_RB[i * 1024 + 512 + j] = (i > j) ? rst : ((i == j) ? r2d[i] : 0.f);
        if (i == j) g_rrii[i] = rs * r2d[i];
    }
}

// ------------------------- preprocessing GEMM body (32x64 tile) --------------
// MODE 0: S = masked(V V^T)   MODE 1: W = V@RB
// MODE 3: [A|Bt] = RB - V^T@X -> fp16 (split for B1, single for B2)
template <int MODE>
__device__ __forceinline__ void pre_body(int m, int n, int k) {
    const float* A; const float* B; int lda, ldb;
    if (MODE == 0) { A = g_V; lda = ZS; B = g_V;  ldb = ZS;   }
    if (MODE == 1) { A = g_V; lda = ZS; B = g_RB; ldb = 1024; }
    if (MODE == 3) { A = g_V; lda = ZS; B = g_W;  ldb = 1024; }

    __shared__ float As[32][17];
    __shared__ float Bs[16][68];
    int tid = threadIdx.x;
    int tx = tid & 15, ty = tid >> 4;
    int i0 = blockIdx.y * 32, j0 = blockIdx.x * 64;

    float acc[2][4] = {};

    for (int k0 = 0; k0 < k; k0 += 16) {
        if (MODE == 3) {
            int ii = tid & 31;
#pragma unroll
            for (int s = 0; s < 2; s++) {
                int kk = (tid >> 5) + s * 8;
                float val = 0.f;
                if (k0 + kk < k && i0 + ii < m)
                    val = A[(size_t)(k0 + kk) * lda + i0 + ii];
                As[ii][kk] = val;
            }
        } else {
            int ii = tid >> 4, kk = tid & 15;
#pragma unroll
            for (int s = 0; s < 2; s++) {
                int iii = ii + s * 16;
                float val = 0.f;
                if (i0 + iii < m && k0 + kk < k)
                    val = A[(size_t)(i0 + iii) * lda + k0 + kk];
                As[iii][kk] = val;
            }
        }
        if (MODE == 0) {
            int jj = tid >> 4, kk = tid & 15;
#pragma unroll
            for (int s = 0; s < 4; s++) {
                int jjj = jj + s * 16;
                float val = 0.f;
                if (j0 + jjj < n && k0 + kk < k)
                    val = B[(size_t)(j0 + jjj) * ldb + k0 + kk];
                Bs[kk][jjj] = val;
            }
        } else {
            int kk = tid >> 6, jj = tid & 63;
#pragma unroll
            for (int s = 0; s < 4; s++) {
                int kkk = kk + s * 4;
                float val = 0.f;
                if (k0 + kkk < k && j0 + jj < n)
                    val = B[(size_t)(k0 + kkk) * ldb + j0 + jj];
                Bs[kkk][jj] = val;
            }
        }
        __syncthreads();
#pragma unroll
        for (int kk = 0; kk < 16; kk++) {
            float a0 = As[ty * 2][kk];
            float a1 = As[ty * 2 + 1][kk];
            float4 bv = *(const float4*)&Bs[kk][tx * 4];
            acc[0][0] = fmaf(a0, bv.x, acc[0][0]);
            acc[0][1] = fmaf(a0, bv.y, acc[0][1]);
            acc[0][2] = fmaf(a0, bv.z, acc[0][2]);
            acc[0][3] = fmaf(a0, bv.w, acc[0][3]);
            acc[1][0] = fmaf(a1, bv.x, acc[1][0]);
            acc[1][1] = fmaf(a1, bv.y, acc[1][1]);
            acc[1][2] = fmaf(a1, bv.z, acc[1][2]);
            acc[1][3] = fmaf(a1, bv.w, acc[1][3]);
        }
        __syncthreads();
    }

#pragma unroll
    for (int r = 0; r < 2; r++) {
        int gi = i0 + ty * 2 + r;
        if (gi >= m) continue;
#pragma unroll
        for (int cc = 0; cc < 4; cc++) {
            int gj = j0 + tx * 4 + cc;
            if (gj >= n) continue;
            float val = acc[r][cc];
            if (MODE == 0) {
                g_S[(size_t)gi * HHN + gj] = (gi < gj) ? val : ((gi == gj) ? 0.5f : 0.f);
            } else if (MODE == 1) {
                g_W[(size_t)gi * 1024 + gj] = val;
            } else {
                float t = g_RB[(size_t)gi * 1024 + gj] - val;
                if (gj < 512) {
                    g_B2h[(size_t)gi * ZS + gj] = __float2half_rn(t);
                } else {
                    __half h, l; split_h(t, h, l);
                    int nn = gj - 512;
                    g_B1h[(size_t)nn * ZS + gi] = h;
                    g_B1l[(size_t)nn * ZS + gi] = l;
                }
            }
        }
    }
}

template <int MODE>
__global__ void __launch_bounds__(256) gemm_pre(int m, int n, int k) {
    pre_body<MODE>(m, n, k);
}

// fused S-gram + W=V@RB. grid (16, 16, 2)
__global__ void __launch_bounds__(256) k_pre01() {
    if (blockIdx.z == 0) {
        if (blockIdx.x >= 8) return;
        if ((int)blockIdx.y * 32 >= (int)blockIdx.x * 64 + 64) return;
        pre_body<0>(HHN, HHN, ZS);
    } else {
        pre_body<1>(HHN, 1024, ZS);
    }
}

// ------------- 128-wide diag solve + fused right-looking update + z-split ----
// Solver CTAs (blockIdx.x < 128): one warp per column; back-substitution with
// x in registers, then apply W[0:rb] -= S[0:rb, rb:rb+mb] @ x for own columns.
// Extra CTAs do z-split slices.
__global__ void __launch_bounds__(256) k_diag128(int b, int zoff,
                                                 const float* __restrict__ z) {
    extern __shared__ float Ss[];   // [128][129]; reused as xs[8][132] after solve
    if (blockIdx.x >= 128) {
        zsplit_block(z, zoff + blockIdx.x - 128);
        return;
    }
    int rb = b * 128;
    int mb = (rb + 128 <= HHN) ? 128 : (HHN - rb);
    int tid = threadIdx.x;

    for (int i = tid; i < 128 * 128; i += 256) {
        int r = i >> 7, col = i & 127;
        float v = 0.f;
        if (r < mb && col < mb) v = g_S[(size_t)(rb + r) * HHN + rb + col];
        Ss[r * 129 + col] = v;
    }
    __syncthreads();

    int w = tid >> 5, lane = tid & 31;
    int c = blockIdx.x * 8 + w;

    float x0 = 0.f, x1 = 0.f, x2 = 0.f, x3 = 0.f;
    if (lane < mb)      x0 = g_W[(size_t)(rb + lane) * 1024 + c];
    if (lane + 32 < mb) x1 = g_W[(size_t)(rb + lane + 32) * 1024 + c];
    if (lane + 64 < mb) x2 = g_W[(size_t)(rb + lane + 64) * 1024 + c];
    if (lane + 96 < mb) x3 = g_W[(size_t)(rb + lane + 96) * 1024 + c];

    for (int i = mb - 1; i > 0; i--) {
        int g4 = i >> 5;
        float src = (g4 == 0) ? x0 : (g4 == 1) ? x1 : (g4 == 2) ? x2 : x3;
        float xi = 2.0f * __shfl_sync(0xffffffffu, src, i & 31);
        if (lane < i)      x0 = fmaf(-Ss[lane * 129 + i], xi, x0);
        if (lane + 32 < i) x1 = fmaf(-Ss[(lane + 32) * 129 + i], xi, x1);
        if (lane + 64 < i) x2 = fmaf(-Ss[(lane + 64) * 129 + i], xi, x2);
        if (lane + 96 < i) x3 = fmaf(-Ss[(lane + 96) * 129 + i], xi, x3);
    }
    x0 *= 2.0f; x1 *= 2.0f; x2 *= 2.0f; x3 *= 2.0f;
    if (lane < mb)      g_W[(size_t)(rb + lane) * 1024 + c]      = x0;
    if (lane + 32 < mb) g_W[(size_t)(rb + lane + 32) * 1024 + c] = x1;
    if (lane + 64 < mb) g_W[(size_t)(rb + lane + 64) * 1024 + c] = x2;
    if (lane + 96 < mb) g_W[(size_t)(rb + lane + 96) * 1024 + c] = x3;

    if (rb == 0) return;

    // ---- fused right-looking update: W[r][c] -= dot(S[r][rb:rb+mb], x) ----
    __syncthreads();                         // done reading Ss
    float* xs = Ss + w * 132;                // 8 warps x 128 (pad 132)
    if (lane < mb)      xs[lane]      = x0;
    if (lane + 32 < mb) xs[lane + 32] = x1;
    if (lane + 64 < mb) xs[lane + 64] = x2;
    if (lane + 96 < mb) xs[lane + 96] = x3;
    __syncwarp();

    for (int r = lane; r < rb; r += 32) {
        const float* Sr = g_S + (size_t)r * HHN + rb;
        float acc = 0.f;
        int j = 0;
#pragma unroll 4
        for (; j + 3 < mb; j += 4) {
            acc = fmaf(__ldg(Sr + j),     xs[j],     acc);
            acc = fmaf(__ldg(Sr + j + 1), xs[j + 1], acc);
            acc = fmaf(__ldg(Sr + j + 2), xs[j + 2], acc);
            acc = fmaf(__ldg(Sr + j + 3), xs[j + 3], acc);
        }
        for (; j < mb; j++) acc = fmaf(__ldg(Sr + j), xs[j], acc);
        g_W[(size_t)r * 1024 + c] -= acc;
    }
}

// ------------------------- HMMA batch GEMM -----------------------------------
// PHASE 0 stage: AH 0 | AL 18432 | BH 36864 | BL 55296  (STG 73728)
// PHASE 1 stage: AH 0 | BH 18432                        (STG 36864)
#define RSTR  144
#define REG   18432

template <int PHASE>
__device__ __forceinline__ void load_stage(uint32_t st,
        const __half* __restrict__ Ah, const __half* __restrict__ Al,
        const __half* __restrict__ Bh, const __half* __restrict__ Bl,
        size_t arow0, int brow0, int k0, int tid) {
    int boffr = (PHASE == 0) ? 2 * REG : REG;
#pragma unroll
    for (int it = 0; it < 4; it++) {
        int u = it * 256 + tid;
        int r = u >> 3, j = u & 7;
        uint32_t sw = (uint32_t)(r * RSTR + j * 16);
        size_t aoff = (arow0 + r) * ZS + k0 + j * 8;
        size_t boff = (size_t)(brow0 + r) * ZS + k0 + j * 8;
        cp16(st + sw, Ah + aoff);
        if (PHASE == 0) cp16(st + REG + sw, Al + aoff);
        cp16(st + boffr + sw, Bh + boff);
        if (PHASE == 0) cp16(st + boffr + REG + sw, Bl + boff);
    }
}

// PHASE 0 (3-pass): D = z@Bt; epi: +c, tanh -> hB (fp16) + ldj partial
// PHASE 1 (1-pass): D = hB@A^T; epi: +z -> zout; finalize ldj
template <int PHASE>
__global__ void __launch_bounds__(256, (PHASE == 0 ? 1 : 2))
k_mma(const float* __restrict__ zin,
      const float* __restrict__ cbias,
      float* __restrict__ out) {
    extern __shared__ char dsm[];

    const int STG   = (PHASE == 0) ? 4 * REG : 2 * REG;  // 73728 / 36864
    const int BOFFR = (PHASE == 0) ? 2 * REG : REG;

    float* c_s  = (float*)(dsm + 2 * STG);
    float* rr_s = c_s + 128;
    float (*sP)[4] = (float(*)[4])(rr_s + 128);

    uint32_t sb = s2u(dsm);
    int tid = threadIdx.x, wid = tid >> 5, lane = tid & 31;
    int wr = wid >> 2, wc = wid & 3;
    int g = lane >> 2, q = lane & 3;
    size_t rowbase = (size_t)blockIdx.x * 128;
    int n0 = blockIdx.y * 128;

    const __half *Ah, *Al, *Bh, *Bl;
    if (PHASE == 0) { Ah = g_zh; Al = g_zl; Bh = g_B1h; Bl = g_B1l; }
    else            { Ah = g_hh; Al = g_hh; Bh = g_B2h; Bl = g_B2h; }

    if (PHASE == 0 && tid < 128) {
        c_s[tid]  = cbias[n0 + tid];
        rr_s[tid] = g_rrii[n0 + tid];
    }
    if (PHASE == 1 && blockIdx.y == 0 && tid < 128) {
        float* ldj = out + (size_t)NB * ZS;
        size_t r = rowbase + tid;
        ldj[r] = g_ldjp[r] + g_ldjp[NB + r] + g_ldjp[2 * NB + r] + g_ldjp[3 * NB + r];
    }

    uint32_t aoffs[4], boffs[2];
#pragma unroll
    for (int mt = 0; mt < 4; mt++)
        aoffs[mt] = (uint32_t)((wr * 64 + mt * 16 + (lane & 15)) * RSTR + (lane >> 4) * 16);
    int nrow = (lane & 7) + ((lane & 16) >> 1);
#pragma unroll
    for (int p = 0; p < 2; p++)
        boffs[p] = (uint32_t)((wc * 32 + p * 16 + nrow) * RSTR + ((lane & 8) ? 16 : 0));

    float    acc [4][4][4];
    uint32_t eacc[4][4][2];
#pragma unroll
    for (int i = 0; i < 4; i++)
#pragma unroll
        for (int j = 0; j < 4; j++) {
#pragma unroll
            for (int r = 0; r < 4; r++) acc[i][j][r] = 0.f;
            eacc[i][j][0] = 0u; eacc[i][j][1] = 0u;
        }

    load_stage<PHASE>(sb, Ah, Al, Bh, Bl, rowbase, n0, 0, tid);
    asm volatile("cp.async.commit_group;" ::: "memory");

#pragma unroll 1
    for (int kc = 0; kc < 8; kc++) {
        if (kc + 1 < 8) {
            load_stage<PHASE>(sb + ((kc + 1) & 1) * STG, Ah, Al, Bh, Bl,
                              rowbase, n0, (kc + 1) * 64, tid);
            asm volatile("cp.async.commit_group;" ::: "memory");
            asm volatile("cp.async.wait_group 1;" ::: "memory");
        } else {
            asm volatile("cp.async.wait_group 0;" ::: "memory");
        }
        __syncthreads();
        uint32_t st = sb + (kc & 1) * STG;
#pragma unroll
        for (int ks = 0; ks < 4; ks++) {
            uint32_t kb = ks * 32;
            uint32_t bH[2][4], bL[2][4];
#pragma unroll
            for (int p = 0; p < 2; p++) {
                LDSM4(bH[p][0], bH[p][1], bH[p][2], bH[p][3], st + BOFFR + boffs[p] + kb);
                if (PHASE == 0)
                    LDSM4(bL[p][0], bL[p][1], bL[p][2], bL[p][3],
                          st + BOFFR + REG + boffs[p] + kb);
            }
#pragma unroll
            for (int mt = 0; mt < 4; mt++) {
                uint32_t aH[4];
                LDSM4(aH[0], aH[1], aH[2], aH[3], st + aoffs[mt] + kb);
                uint32_t aL[4];
                if (PHASE == 0)
                    LDSM4(aL[0], aL[1], aL[2], aL[3], st + REG + aoffs[mt] + kb);
#pragma unroll
                for (int nt = 0; nt < 4; nt++) {
                    int p = nt >> 1, s2 = (nt & 1) * 2;
                    MMA(acc[mt][nt], aH, bH[p][s2], bH[p][s2 + 1]);
                    if (PHASE == 0) {
                        MMAH(eacc[mt][nt], aH, bL[p][s2], bL[p][s2 + 1]);
                        MMAH(eacc[mt][nt], aL, bH[p][s2], bH[p][s2 + 1]);
                    }
                }
            }
        }
        __syncthreads();
    }

    // ------------------------- epilogue -------------------------
    if (PHASE == 0) {
        float lp0[4], lp1[4];
#pragma unroll
        for (int mt = 0; mt < 4; mt++) { lp0[mt] = 0.f; lp1[mt] = 0.f; }
#pragma unroll
        for (int mt = 0; mt < 4; mt++) {
            int r0 = wr * 64 + mt * 16 + g;
            size_t gr0 = (rowbase + r0) * ZS + n0;
            size_t gr1 = gr0 + 8 * ZS;
#pragma unroll
            for (int nt = 0; nt < 4; nt++) {
                int cl = wc * 32 + nt * 8 + q * 2;
                __half2 e0 = *(__half2*)&eacc[mt][nt][0];
                __half2 e1 = *(__half2*)&eacc[mt][nt][1];
                float t00 = acc[mt][nt][0] + __low2float(e0)  + c_s[cl];
                float t01 = acc[mt][nt][1] + __high2float(e0) + c_s[cl + 1];
                float t10 = acc[mt][nt][2] + __low2float(e1)  + c_s[cl];
                float t11 = acc[mt][nt][3] + __high2float(e1) + c_s[cl + 1];
                float h00 = ftanh(t00), h01 = ftanh(t01);
                float h10 = ftanh(t10), h11 = ftanh(t11);
                lp0[mt] += __logf(fabsf(fmaf(1.f - h00 * h00, rr_s[cl], 1.f)))
                         + __logf(fabsf(fmaf(1.f - h01 * h01, rr_s[cl + 1], 1.f)));
                lp1[mt] += __logf(fabsf(fmaf(1.f - h10 * h10, rr_s[cl], 1.f)))
                         + __logf(fabsf(fmaf(1.f - h11 * h11, rr_s[cl + 1], 1.f)));
                *(__half2*)(g_hh + gr0 + cl) = __floats2half2_rn(h00, h01);
                *(__half2*)(g_hh + gr1 + cl) = __floats2half2_rn(h10, h11);
            }
            lp0[mt] += __shfl_xor_sync(0xffffffffu, lp0[mt], 1);
            lp0[mt] += __shfl_xor_sync(0xffffffffu, lp0[mt], 2);
            lp1[mt] += __shfl_xor_sync(0xffffffffu, lp1[mt], 1);
            lp1[mt] += __shfl_xor_sync(0xffffffffu, lp1[mt], 2);
            if (q == 0) {
                sP[r0][wc]     = lp0[mt];
                sP[r0 + 8][wc] = lp1[mt];
            }
        }
        __syncthreads();
        if (tid < 128)
            g_ldjp[(size_t)blockIdx.y * NB + rowbase + tid] =
                sP[tid][0] + sP[tid][1] + sP[tid][2] + sP[tid][3];
    } else {
#pragma unroll
        for (int mt = 0; mt < 4; mt++) {
            int r0 = wr * 64 + mt * 16 + g;
            size_t gr0 = (rowbase + r0) * ZS + n0;
            size_t gr1 = gr0 + 8 * ZS;
#pragma unroll
            for (int nt = 0; nt < 4; nt++) {
                int cl = wc * 32 + nt * 8 + q * 2;
                float2 z0 = *(const float2*)(zin + gr0 + cl);
                float2 z1 = *(const float2*)(zin + gr1 + cl);
                float2 o0, o1;
                o0.x = acc[mt][nt][0] + z0.x;
                o0.y = acc[mt][nt][1] + z0.y;
                o1.x = acc[mt][nt][2] + z1.x;
                o1.y = acc[mt][nt][3] + z1.y;
                *(float2*)(out + gr0 + cl) = o0;
                *(float2*)(out + gr1 + cl) = o1;
            }
        }
    }
}

// ------------------------- launch -------------------------------------------
extern "C" void kernel_launch(void* const* d_in, const int* in_sizes, int n_in,
                              void* d_out, int out_size) {
    const float* z   = (const float*)d_in[0];
    const float* v   = (const float*)d_in[1];
    const float* Rs  = (const float*)d_in[2];
    const float* r2d = (const float*)d_in[3];
    const float* c   = (const float*)d_in[4];
    float* out = (float*)d_out;

    k_init<<<HHN + 1024, 256>>>(v, Rs, r2d);
    k_pre01<<<dim3(16, 16, 2), 256>>>();

    // 4-launch solve: 128-wide diag + fused right-looking update + z-split
    int dsmS = 128 * 129 * 4;   // 66048
    cudaFuncSetAttribute(k_diag128, cudaFuncAttributeMaxDynamicSharedMemorySize, dsmS);
    for (int b = 3; b >= 0; b--)
        k_diag128<<<128 + 4096, 256, dsmS>>>(b, (3 - b) * 4096, z);

    gemm_pre<3><<<dim3(16, 16), 256>>>(ZS, 1024, HHN);

    int dsm0 = 2 * 73728 + 3072;  // phase 0: 3-pass stages + c_s/rr_s/sP
    int dsm1 = 2 * 36864;         // phase 1: 1-pass stages; 2 CTAs/SM
    cudaFuncSetAttribute(k_mma<0>, cudaFuncAttributeMaxDynamicSharedMemorySize, dsm0);
    cudaFuncSetAttribute(k_mma<1>, cudaFuncAttributeMaxDynamicSharedMemorySize, dsm1);
    k_mma<0><<<dim3(NB / 128, 4), 256, dsm0>>>(z, c, out);
    k_mma<1><<<dim3(NB / 128, 4), 256, dsm1>>>(z, c, out);
}

// round 17
// speedup vs baseline: 1.3266x; 1.3266x over previous
#include <cuda_runtime.h>
#include <cuda_fp16.h>
#include <cstdint>

#define ZS   512
#define HHN  511
#define NB   65536

// ------------------------- device scratch (no allocs) -----------------------
__device__ float g_V [HHN * ZS];
__device__ float g_RB[ZS * 1024];
__device__ float g_S [HHN * HHN];
__device__ float g_W [HHN * 1024];
__device__ float g_rrii[ZS];
__device__ float g_ldjp[4 * NB];
__device__ __align__(16) __half g_B1h[ZS * ZS], g_B1l[ZS * ZS]; // [n][k]
__device__ __align__(16) __half g_B2h[ZS * ZS];                 // [zi][n]
__device__ __align__(16) __half g_zh[(size_t)NB * ZS];          // z hi
__device__ __align__(16) __half g_zl[(size_t)NB * ZS];          // z lo
__device__ __align__(16) __half g_hh[(size_t)NB * ZS];          // hB (fp16)

// ------------------------- helpers ------------------------------------------
__device__ __forceinline__ float ftanh(float x) {
    float ax = fabsf(x);
    float e  = __expf(-2.0f * ax);
    float t  = __fdividef(1.0f - e, 1.0f + e);
    return copysignf(t, x);
}
__device__ __forceinline__ uint32_t s2u(const void* p) {
    uint32_t a;
    asm("{ .reg .u64 t; cvta.to.shared.u64 t, %1; cvt.u32.u64 %0, t; }" : "=r"(a) : "l"(p));
    return a;
}
__device__ __forceinline__ void cp16(uint32_t d, const void* s) {
    asm volatile("cp.async.cg.shared.global [%0], [%1], 16;\n" :: "r"(d), "l"(s));
}
#define LDSM4(r0, r1, r2, r3, a) \
    asm volatile("ldmatrix.sync.aligned.m8n8.x4.shared.b16 {%0,%1,%2,%3}, [%4];" \
                 : "=r"(r0), "=r"(r1), "=r"(r2), "=r"(r3) : "r"(a))
#define MMA(c, a, b0, b1) \
    asm volatile("mma.sync.aligned.m16n8k16.row.col.f32.f16.f16.f32 " \
                 "{%0,%1,%2,%3},{%4,%5,%6,%7},{%8,%9},{%0,%1,%2,%3};" \
                 : "+f"((c)[0]), "+f"((c)[1]), "+f"((c)[2]), "+f"((c)[3]) \
                 : "r"((a)[0]), "r"((a)[1]), "r"((a)[2]), "r"((a)[3]), "r"(b0), "r"(b1))
#define MMAH(e, a, b0, b1) \
    asm volatile("mma.sync.aligned.m16n8k16.row.col.f16.f16.f16.f16 " \
                 "{%0,%1},{%2,%3,%4,%5},{%6,%7},{%0,%1};" \
                 : "+r"((e)[0]), "+r"((e)[1]) \
                 : "r"((a)[0]), "r"((a)[1]), "r"((a)[2]), "r"((a)[3]), "r"(b0), "r"(b1))

__device__ __forceinline__ void split_h(float x, __half& h, __half& l) {
    h = __float2half_rn(x);
    l = __float2half_rn(x - __half2float(h));
}

// one z-split block: 2048 floats -> fp16 hi/lo
__device__ __forceinline__ void zsplit_block(const float* __restrict__ z, int zb) {
    size_t base = ((size_t)zb * 256 + threadIdx.x) * 8;
    float4 a = *(const float4*)(z + base);
    float4 b = *(const float4*)(z + base + 4);
    float x[8] = {a.x, a.y, a.z, a.w, b.x, b.y, b.z, b.w};
    __half2 hh[4], ll[4];
#pragma unroll
    for (int i = 0; i < 4; i++) {
        __half h0, l0, h1, l1;
        split_h(x[2 * i], h0, l0);
        split_h(x[2 * i + 1], h1, l1);
        hh[i] = __halves2half2(h0, h1);
        ll[i] = __halves2half2(l0, l1);
    }
    *(uint4*)(g_zh + base) = *(uint4*)hh;
    *(uint4*)(g_zl + base) = *(uint4*)ll;
}

// ------------------------- init: normalize v | build RB ----------------------
__global__ void __launch_bounds__(256) k_init(const float* __restrict__ v,
                                              const float* __restrict__ Rs,
                                              const float* __restrict__ r2d) {
    int tid = threadIdx.x;
    if (blockIdx.x < HHN) {
        int row = blockIdx.x;
        float x0 = v[row * ZS + tid];
        float x1 = v[row * ZS + tid + 256];
        float s = x0 * x0 + x1 * x1;
#pragma unroll
        for (int o = 16; o > 0; o >>= 1) s += __shfl_xor_sync(0xffffffffu, s, o);
        __shared__ float red[8];
        __shared__ float sinv;
        if ((tid & 31) == 0) red[tid >> 5] = s;
        __syncthreads();
        if (tid == 0) {
            float t = 0.f;
#pragma unroll
            for (int i = 0; i < 8; i++) t += red[i];
            sinv = rsqrtf(t);
        }
        __syncthreads();
        float inv = sinv;
        g_V[row * ZS + tid]       = x0 * inv;
        g_V[row * ZS + tid + 256] = x1 * inv;
    } else {
        int idx = (blockIdx.x - HHN) * 256 + tid;
        int i = idx >> 9, j = idx & 511;
        float rs = Rs[i * ZS + j];
        g_RB[i * 1024 + j] = (j >= i) ? rs : 0.f;
        float rst = Rs[j * ZS + i];
        g_RB[i * 1024 + 512 + j] = (i > j) ? rst : ((i == j) ? r2d[i] : 0.f);
        if (i == j) g_rrii[i] = rs * r2d[i];
    }
}

// ------------------------- preprocessing GEMM body (32x64 tile) --------------
// MODE 0: S = masked(V V^T)   MODE 1: W = V@RB   MODE 2: C -= A@B (right-look)
// MODE 3: [A|Bt] = RB - V^T@X -> fp16 (split for B1, single for B2)
template <int MODE>
__device__ __forceinline__ void pre_body(int m, int n, int k,
                                         int aoff, int boff, int coff) {
    const float* A; const float* B; int lda, ldb;
    if (MODE == 0) { A = g_V;        lda = ZS;  B = g_V;        ldb = ZS;   }
    if (MODE == 1) { A = g_V;        lda = ZS;  B = g_RB;       ldb = 1024; }
    if (MODE == 2) { A = g_S + aoff; lda = HHN; B = g_W + boff; ldb = 1024; }
    if (MODE == 3) { A = g_V;        lda = ZS;  B = g_W;        ldb = 1024; }

    __shared__ float As[32][17];
    __shared__ float Bs[16][68];
    int tid = threadIdx.x;
    int tx = tid & 15, ty = tid >> 4;
    int i0 = blockIdx.y * 32, j0 = blockIdx.x * 64;

    float acc[2][4] = {};

    for (int k0 = 0; k0 < k; k0 += 16) {
        if (MODE == 3) {
            int ii = tid & 31;
#pragma unroll
            for (int s = 0; s < 2; s++) {
                int kk = (tid >> 5) + s * 8;
                float val = 0.f;
                if (k0 + kk < k && i0 + ii < m)
                    val = A[(size_t)(k0 + kk) * lda + i0 + ii];
                As[ii][kk] = val;
            }
        } else {
            int ii = tid >> 4, kk = tid & 15;
#pragma unroll
            for (int s = 0; s < 2; s++) {
                int iii = ii + s * 16;
                float val = 0.f;
                if (i0 + iii < m && k0 + kk < k)
                    val = A[(size_t)(i0 + iii) * lda + k0 + kk];
                As[iii][kk] = val;
            }
        }
        if (MODE == 0) {
            int jj = tid >> 4, kk = tid & 15;
#pragma unroll
            for (int s = 0; s < 4; s++) {
                int jjj = jj + s * 16;
                float val = 0.f;
                if (j0 + jjj < n && k0 + kk < k)
                    val = B[(size_t)(j0 + jjj) * ldb + k0 + kk];
                Bs[kk][jjj] = val;
            }
        } else {
            int kk = tid >> 6, jj = tid & 63;
#pragma unroll
            for (int s = 0; s < 4; s++) {
                int kkk = kk + s * 4;
                float val = 0.f;
                if (k0 + kkk < k && j0 + jj < n)
                    val = B[(size_t)(k0 + kkk) * ldb + j0 + jj];
                Bs[kkk][jj] = val;
            }
        }
        __syncthreads();
#pragma unroll
        for (int kk = 0; kk < 16; kk++) {
            float a0 = As[ty * 2][kk];
            float a1 = As[ty * 2 + 1][kk];
            float4 bv = *(const float4*)&Bs[kk][tx * 4];
            acc[0][0] = fmaf(a0, bv.x, acc[0][0]);
            acc[0][1] = fmaf(a0, bv.y, acc[0][1]);
            acc[0][2] = fmaf(a0, bv.z, acc[0][2]);
            acc[0][3] = fmaf(a0, bv.w, acc[0][3]);
            acc[1][0] = fmaf(a1, bv.x, acc[1][0]);
            acc[1][1] = fmaf(a1, bv.y, acc[1][1]);
            acc[1][2] = fmaf(a1, bv.z, acc[1][2]);
            acc[1][3] = fmaf(a1, bv.w, acc[1][3]);
        }
        __syncthreads();
    }

#pragma unroll
    for (int r = 0; r < 2; r++) {
        int gi = i0 + ty * 2 + r;
        if (gi >= m) continue;
#pragma unroll
        for (int cc = 0; cc < 4; cc++) {
            int gj = j0 + tx * 4 + cc;
            if (gj >= n) continue;
            float val = acc[r][cc];
            if (MODE == 0) {
                g_S[(size_t)gi * HHN + gj] = (gi < gj) ? val : ((gi == gj) ? 0.5f : 0.f);
            } else if (MODE == 1) {
                g_W[(size_t)gi * 1024 + gj] = val;
            } else if (MODE == 2) {
                float* C = g_W + coff;
                C[(size_t)gi * 1024 + gj] = C[(size_t)gi * 1024 + gj] - val;
            } else {
                float t = g_RB[(size_t)gi * 1024 + gj] - val;
                if (gj < 512) {
                    g_B2h[(size_t)gi * ZS + gj] = __float2half_rn(t);
                } else {
                    __half h, l; split_h(t, h, l);
                    int nn = gj - 512;
                    g_B1h[(size_t)nn * ZS + gi] = h;
                    g_B1l[(size_t)nn * ZS + gi] = l;
                }
            }
        }
    }
}

template <int MODE>
__global__ void __launch_bounds__(256) gemm_pre(int m, int n, int k,
                                                int aoff, int boff, int coff) {
    pre_body<MODE>(m, n, k, aoff, boff, coff);
}

// fused S-gram + W=V@RB. grid (16, 16, 2)
__global__ void __launch_bounds__(256) k_pre01() {
    if (blockIdx.z == 0) {
        if (blockIdx.x >= 8) return;
        if ((int)blockIdx.y * 32 >= (int)blockIdx.x * 64 + 64) return;
        pre_body<0>(HHN, HHN, ZS, 0, 0, 0);
    } else {
        pre_body<1>(HHN, 1024, ZS, 0, 0, 0);
    }
}

// ------------------------- 128-wide diag solve + co-resident z-split ---------
// Solver CTAs (blockIdx.x < 128): one warp per column, reduction-free
// back-substitution with x in registers. Extra CTAs do z-split slices.
__global__ void __launch_bounds__(256) k_diag128(int b, int zoff,
                                                 const float* __restrict__ z) {
    extern __shared__ float Ss[];   // [128][129]
    if (blockIdx.x >= 128) {
        zsplit_block(z, zoff + blockIdx.x - 128);
        return;
    }
    int rb = b * 128;
    int mb = (rb + 128 <= HHN) ? 128 : (HHN - rb);
    int tid = threadIdx.x;

    for (int i = tid; i < 128 * 128; i += 256) {
        int r = i >> 7, col = i & 127;
        float v = 0.f;
        if (r < mb && col < mb) v = g_S[(size_t)(rb + r) * HHN + rb + col];
        Ss[r * 129 + col] = v;
    }
    __syncthreads();

    int w = tid >> 5, lane = tid & 31;
    int c = blockIdx.x * 8 + w;

    float x0 = 0.f, x1 = 0.f, x2 = 0.f, x3 = 0.f;
    if (lane < mb)      x0 = g_W[(size_t)(rb + lane) * 1024 + c];
    if (lane + 32 < mb) x1 = g_W[(size_t)(rb + lane + 32) * 1024 + c];
    if (lane + 64 < mb) x2 = g_W[(size_t)(rb + lane + 64) * 1024 + c];
    if (lane + 96 < mb) x3 = g_W[(size_t)(rb + lane + 96) * 1024 + c];

    for (int i = mb - 1; i > 0; i--) {
        int g4 = i >> 5;
        float src = (g4 == 0) ? x0 : (g4 == 1) ? x1 : (g4 == 2) ? x2 : x3;
        float xi = 2.0f * __shfl_sync(0xffffffffu, src, i & 31);
        if (lane < i)      x0 = fmaf(-Ss[lane * 129 + i], xi, x0);
        if (lane + 32 < i) x1 = fmaf(-Ss[(lane + 32) * 129 + i], xi, x1);
        if (lane + 64 < i) x2 = fmaf(-Ss[(lane + 64) * 129 + i], xi, x2);
        if (lane + 96 < i) x3 = fmaf(-Ss[(lane + 96) * 129 + i], xi, x3);
    }
    if (lane < mb)      g_W[(size_t)(rb + lane) * 1024 + c]      = 2.0f * x0;
    if (lane + 32 < mb) g_W[(size_t)(rb + lane + 32) * 1024 + c] = 2.0f * x1;
    if (lane + 64 < mb) g_W[(size_t)(rb + lane + 64) * 1024 + c] = 2.0f * x2;
    if (lane + 96 < mb) g_W[(size_t)(rb + lane + 96) * 1024 + c] = 2.0f * x3;
}

// ------------------------- HMMA batch GEMM -----------------------------------
// PHASE 0 stage: AH 0 | AL 18432 | BH 36864 | BL 55296  (STG 73728)
// PHASE 1 stage: AH 0 | BH 18432                        (STG 36864)
#define RSTR  144
#define REG   18432

template <int PHASE>
__device__ __forceinline__ void load_stage(uint32_t st,
        const __half* __restrict__ Ah, const __half* __restrict__ Al,
        const __half* __restrict__ Bh, const __half* __restrict__ Bl,
        size_t arow0, int brow0, int k0, int tid) {
    int boffr = (PHASE == 0) ? 2 * REG : REG;
#pragma unroll
    for (int it = 0; it < 4; it++) {
        int u = it * 256 + tid;
        int r = u >> 3, j = u & 7;
        uint32_t sw = (uint32_t)(r * RSTR + j * 16);
        size_t aoff = (arow0 + r) * ZS + k0 + j * 8;
        size_t boff = (size_t)(brow0 + r) * ZS + k0 + j * 8;
        cp16(st + sw, Ah + aoff);
        if (PHASE == 0) cp16(st + REG + sw, Al + aoff);
        cp16(st + boffr + sw, Bh + boff);
        if (PHASE == 0) cp16(st + boffr + REG + sw, Bl + boff);
    }
}

// PHASE 0 (3-pass): D = z@Bt; epi: +c, tanh -> hB (fp16) + ldj partial
// PHASE 1 (1-pass): D = hB@A^T; epi: +z -> zout; finalize ldj
template <int PHASE>
__global__ void __launch_bounds__(256, (PHASE == 0 ? 1 : 2))
k_mma(const float* __restrict__ zin,
      const float* __restrict__ cbias,
      float* __restrict__ out) {
    extern __shared__ char dsm[];

    const int STG   = (PHASE == 0) ? 4 * REG : 2 * REG;  // 73728 / 36864
    const int BOFFR = (PHASE == 0) ? 2 * REG : REG;

    float* c_s  = (float*)(dsm + 2 * STG);
    float* rr_s = c_s + 128;
    float (*sP)[4] = (float(*)[4])(rr_s + 128);

    uint32_t sb = s2u(dsm);
    int tid = threadIdx.x, wid = tid >> 5, lane = tid & 31;
    int wr = wid >> 2, wc = wid & 3;
    int g = lane >> 2, q = lane & 3;
    size_t rowbase = (size_t)blockIdx.x * 128;
    int n0 = blockIdx.y * 128;

    const __half *Ah, *Al, *Bh, *Bl;
    if (PHASE == 0) { Ah = g_zh; Al = g_zl; Bh = g_B1h; Bl = g_B1l; }
    else            { Ah = g_hh; Al = g_hh; Bh = g_B2h; Bl = g_B2h; }

    if (PHASE == 0 && tid < 128) {
        c_s[tid]  = cbias[n0 + tid];
        rr_s[tid] = g_rrii[n0 + tid];
    }
    if (PHASE == 1 && blockIdx.y == 0 && tid < 128) {
        float* ldj = out + (size_t)NB * ZS;
        size_t r = rowbase + tid;
        ldj[r] = g_ldjp[r] + g_ldjp[NB + r] + g_ldjp[2 * NB + r] + g_ldjp[3 * NB + r];
    }

    uint32_t aoffs[4], boffs[2];
#pragma unroll
    for (int mt = 0; mt < 4; mt++)
        aoffs[mt] = (uint32_t)((wr * 64 + mt * 16 + (lane & 15)) * RSTR + (lane >> 4) * 16);
    int nrow = (lane & 7) + ((lane & 16) >> 1);
#pragma unroll
    for (int p = 0; p < 2; p++)
        boffs[p] = (uint32_t)((wc * 32 + p * 16 + nrow) * RSTR + ((lane & 8) ? 16 : 0));

    float    acc [4][4][4];
    uint32_t eacc[4][4][2];
#pragma unroll
    for (int i = 0; i < 4; i++)
#pragma unroll
        for (int j = 0; j < 4; j++) {
#pragma unroll
            for (int r = 0; r < 4; r++) acc[i][j][r] = 0.f;
            eacc[i][j][0] = 0u; eacc[i][j][1] = 0u;
        }

    load_stage<PHASE>(sb, Ah, Al, Bh, Bl, rowbase, n0, 0, tid);
    asm volatile("cp.async.commit_group;" ::: "memory");

#pragma unroll 1
    for (int kc = 0; kc < 8; kc++) {
        if (kc + 1 < 8) {
            load_stage<PHASE>(sb + ((kc + 1) & 1) * STG, Ah, Al, Bh, Bl,
                              rowbase, n0, (kc + 1) * 64, tid);
            asm volatile("cp.async.commit_group;" ::: "memory");
            asm volatile("cp.async.wait_group 1;" ::: "memory");
        } else {
            asm volatile("cp.async.wait_group 0;" ::: "memory");
        }
        __syncthreads();
        uint32_t st = sb + (kc & 1) * STG;
#pragma unroll
        for (int ks = 0; ks < 4; ks++) {
            uint32_t kb = ks * 32;
            uint32_t bH[2][4], bL[2][4];
#pragma unroll
            for (int p = 0; p < 2; p++) {
                LDSM4(bH[p][0], bH[p][1], bH[p][2], bH[p][3], st + BOFFR + boffs[p] + kb);
                if (PHASE == 0)
                    LDSM4(bL[p][0], bL[p][1], bL[p][2], bL[p][3],
                          st + BOFFR + REG + boffs[p] + kb);
            }
#pragma unroll
            for (int mt = 0; mt < 4; mt++) {
                uint32_t aH[4];
                LDSM4(aH[0], aH[1], aH[2], aH[3], st + aoffs[mt] + kb);
                uint32_t aL[4];
                if (PHASE == 0)
                    LDSM4(aL[0], aL[1], aL[2], aL[3], st + REG + aoffs[mt] + kb);
#pragma unroll
                for (int nt = 0; nt < 4; nt++) {
                    int p = nt >> 1, s2 = (nt & 1) * 2;
                    MMA(acc[mt][nt], aH, bH[p][s2], bH[p][s2 + 1]);
                    if (PHASE == 0) {
                        MMAH(eacc[mt][nt], aH, bL[p][s2], bL[p][s2 + 1]);
                        MMAH(eacc[mt][nt], aL, bH[p][s2], bH[p][s2 + 1]);
                    }
                }
            }
        }
        __syncthreads();
    }

    // ------------------------- epilogue -------------------------
    if (PHASE == 0) {
        float lp0[4], lp1[4];
#pragma unroll
        for (int mt = 0; mt < 4; mt++) { lp0[mt] = 0.f; lp1[mt] = 0.f; }
#pragma unroll
        for (int mt = 0; mt < 4; mt++) {
            int r0 = wr * 64 + mt * 16 + g;
            size_t gr0 = (rowbase + r0) * ZS + n0;
            size_t gr1 = gr0 + 8 * ZS;
#pragma unroll
            for (int nt = 0; nt < 4; nt++) {
                int cl = wc * 32 + nt * 8 + q * 2;
                __half2 e0 = *(__half2*)&eacc[mt][nt][0];
                __half2 e1 = *(__half2*)&eacc[mt][nt][1];
                float t00 = acc[mt][nt][0] + __low2float(e0)  + c_s[cl];
                float t01 = acc[mt][nt][1] + __high2float(e0) + c_s[cl + 1];
                float t10 = acc[mt][nt][2] + __low2float(e1)  + c_s[cl];
                float t11 = acc[mt][nt][3] + __high2float(e1) + c_s[cl + 1];
                float h00 = ftanh(t00), h01 = ftanh(t01);
                float h10 = ftanh(t10), h11 = ftanh(t11);
                lp0[mt] += __logf(fabsf(fmaf(1.f - h00 * h00, rr_s[cl], 1.f)))
                         + __logf(fabsf(fmaf(1.f - h01 * h01, rr_s[cl + 1], 1.f)));
                lp1[mt] += __logf(fabsf(fmaf(1.f - h10 * h10, rr_s[cl], 1.f)))
                         + __logf(fabsf(fmaf(1.f - h11 * h11, rr_s[cl + 1], 1.f)));
                *(__half2*)(g_hh + gr0 + cl) = __floats2half2_rn(h00, h01);
                *(__half2*)(g_hh + gr1 + cl) = __floats2half2_rn(h10, h11);
            }
            lp0[mt] += __shfl_xor_sync(0xffffffffu, lp0[mt], 1);
            lp0[mt] += __shfl_xor_sync(0xffffffffu, lp0[mt], 2);
            lp1[mt] += __shfl_xor_sync(0xffffffffu, lp1[mt], 1);
            lp1[mt] += __shfl_xor_sync(0xffffffffu, lp1[mt], 2);
            if (q == 0) {
                sP[r0][wc]     = lp0[mt];
                sP[r0 + 8][wc] = lp1[mt];
            }
        }
        __syncthreads();
        if (tid < 128)
            g_ldjp[(size_t)blockIdx.y * NB + rowbase + tid] =
                sP[tid][0] + sP[tid][1] + sP[tid][2] + sP[tid][3];
    } else {
#pragma unroll
        for (int mt = 0; mt < 4; mt++) {
            int r0 = wr * 64 + mt * 16 + g;
            size_t gr0 = (rowbase + r0) * ZS + n0;
            size_t gr1 = gr0 + 8 * ZS;
#pragma unroll
            for (int nt = 0; nt < 4; nt++) {
                int cl = wc * 32 + nt * 8 + q * 2;
                float2 z0 = *(const float2*)(zin + gr0 + cl);
                float2 z1 = *(const float2*)(zin + gr1 + cl);
                float2 o0, o1;
                o0.x = acc[mt][nt][0] + z0.x;
                o0.y = acc[mt][nt][1] + z0.y;
                o1.x = acc[mt][nt][2] + z1.x;
                o1.y = acc[mt][nt][3] + z1.y;
                *(float2*)(out + gr0 + cl) = o0;
                *(float2*)(out + gr1 + cl) = o1;
            }
        }
    }
}

// ------------------------- launch -------------------------------------------
extern "C" void kernel_launch(void* const* d_in, const int* in_sizes, int n_in,
                              void* d_out, int out_size) {
    const float* z   = (const float*)d_in[0];
    const float* v   = (const float*)d_in[1];
    const float* Rs  = (const float*)d_in[2];
    const float* r2d = (const float*)d_in[3];
    const float* c   = (const float*)d_in[4];
    float* out = (float*)d_out;

    k_init<<<HHN + 1024, 256>>>(v, Rs, r2d);
    k_pre01<<<dim3(16, 16, 2), 256>>>();

    // 128-wide right-looking solve; each diag carries 4096 z-split CTAs
    int dsmS = 128 * 129 * 4;   // 66048
    cudaFuncSetAttribute(k_diag128, cudaFuncAttributeMaxDynamicSharedMemorySize, dsmS);
    for (int b = 3; b >= 0; b--) {
        int rb = b * 128;
        int mb = (rb + 128 <= HHN) ? 128 : (HHN - rb);
        k_diag128<<<128 + 4096, 256, dsmS>>>(b, (3 - b) * 4096, z);
        if (b > 0)
            gemm_pre<2><<<dim3(16, rb / 32), 256>>>(rb, 1024, mb,
                                                    rb, rb * 1024, 0);
    }

    gemm_pre<3><<<dim3(16, 16), 256>>>(ZS, 1024, HHN, 0, 0, 0);

    int dsm0 = 2 * 73728 + 3072;  // phase 0: 3-pass stages + c_s/rr_s/sP
    int dsm1 = 2 * 36864;         // phase 1: 1-pass stages; 2 CTAs/SM
    cudaFuncSetAttribute(k_mma<0>, cudaFuncAttributeMaxDynamicSharedMemorySize, dsm0);
    cudaFuncSetAttribute(k_mma<1>, cudaFuncAttributeMaxDynamicSharedMemorySize, dsm1);
    k_mma<0><<<dim3(NB / 128, 4), 256, dsm0>>>(z, c, out);
    k_mma<1><<<dim3(NB / 128, 4), 256, dsm1>>>(z, c, out);
}